// round 15
// baseline (speedup 1.0000x reference)
#include <cuda_runtime.h>
#include <cuda_fp16.h>
#include <cstdint>

// ---------------- problem constants ----------------
#define NTOK   2048
#define EMB    512
#define HD     512
#define NSEG   32
#define SEGLEN 64
#define MAXM   40960
#define MAXC   20
#define KP     512             // pure fp16 for GEMM2/3 (noise cancels; measured)
#define KW     1024            // fp16x2 for GEMM1 (prefix-diff amplification!)
#define MW     2049
#define MWPAD  2176

#define OFF_START 0
#define OFF_END   2048
#define OFF_LEN   4097
#define OFF_MID   4118
#define TROWS     8214

// ---------------- device scratch ----------------
__device__ __half g_csumH[(size_t)MWPAD * KW];
__device__ float g_csumW[(size_t)MW * HD];
__device__ __half g_TposH[(size_t)TROWS * HD];
__device__ float g_segsum[NSEG * EMB];
__device__ float g_segoff[NSEG * EMB];
__device__ float g_partial[MAXM * 4];
__device__ __half g_hA[(size_t)MAXM * KP];
__device__ __half g_pA[(size_t)MAXM * KP];
__device__ __half g_w1h[(size_t)512 * KP];
__device__ __half g_w3h[(size_t)512 * KP];
__device__ __half g_w0h[(size_t)512 * KW];

// ---------------- PTX helpers (plain sm_80+ features only) ----------------
__device__ __forceinline__ uint32_t smem_u32(const void* p) {
    uint32_t a;
    asm("{ .reg .u64 t; cvta.to.shared.u64 t, %1; cvt.u32.u64 %0, t; }" : "=r"(a) : "l"(p));
    return a;
}
__device__ __forceinline__ void cpa16(uint32_t dst, const void* src) {
    asm volatile("cp.async.cg.shared.global [%0], [%1], 16;" :: "r"(dst), "l"(src));
}
__device__ __forceinline__ uint32_t swz(uint32_t o) { return o ^ ((o >> 3) & 0x70); }

#define LDMX4(r, addr) \
    asm volatile("ldmatrix.sync.aligned.m8n8.x4.shared.b16 {%0,%1,%2,%3}, [%4];" \
        : "=r"((r)[0]), "=r"((r)[1]), "=r"((r)[2]), "=r"((r)[3]) : "r"(addr))

#define MMA16816(c, a, b) \
    asm volatile("mma.sync.aligned.m16n8k16.row.col.f32.f16.f16.f32 " \
        "{%0,%1,%2,%3}, {%4,%5,%6,%7}, {%8,%9}, {%0,%1,%2,%3};" \
        : "+f"((c)[0]), "+f"((c)[1]), "+f"((c)[2]), "+f"((c)[3]) \
        : "r"((a)[0]), "r"((a)[1]), "r"((a)[2]), "r"((a)[3]), "r"((b)[0]), "r"((b)[1]))

// ---------------- token prefix sums ----------------
__device__ __forceinline__ float embval(const int* __restrict__ sent,
                                        const int* __restrict__ tags,
                                        const float* __restrict__ Wwrd,
                                        const float* __restrict__ Wpos,
                                        int t, int col) {
    if (col < 256) return Wpos[tags[t] * 256 + col];
    return Wwrd[(size_t)sent[t] * 256 + (col - 256)];
}
__global__ void k_segsum(const int* __restrict__ sent, const int* __restrict__ tags,
                         const float* __restrict__ Wwrd, const float* __restrict__ Wpos) {
    int seg = blockIdx.x;
    int col = blockIdx.y * 256 + threadIdx.x;
    float acc = 0.f;
    int t0 = seg * SEGLEN;
    for (int t = t0; t < t0 + SEGLEN; t++) acc += embval(sent, tags, Wwrd, Wpos, t, col);
    g_segsum[seg * EMB + col] = acc;
}
__global__ void k_segscan() {
    int col = threadIdx.x;
    float run = 0.f;
    for (int s = 0; s < NSEG; s++) {
        float v = g_segsum[s * EMB + col];
        g_segoff[s * EMB + col] = run;
        run += v;
    }
}
__global__ void k_csum(const int* __restrict__ sent, const int* __restrict__ tags,
                       const float* __restrict__ Wwrd, const float* __restrict__ Wpos) {
    int seg = blockIdx.x;
    int col = blockIdx.y * 256 + threadIdx.x;
    float acc = g_segoff[seg * EMB + col];
    if (seg == 0) {
        g_csumH[col] = __float2half_rn(0.f);
        g_csumH[512 + col] = __float2half_rn(0.f);
    }
    int t0 = seg * SEGLEN;
    for (int t = t0; t < t0 + SEGLEN; t++) {
        acc += embval(sent, tags, Wwrd, Wpos, t, col);
        __half hi = __float2half_rn(acc);
        __half lo = __float2half_rn(acc - __half2float(hi));
        g_csumH[(size_t)(t + 1) * KW + col] = hi;
        g_csumH[(size_t)(t + 1) * KW + 512 + col] = lo;
    }
}

// ---------------- positional tables (tiled; weight slice staged in smem) ----
// grid (256, 2, 4): z = table, x = 16-row group, y = 256-col half.
__global__ void __launch_bounds__(256, 2) k_tables(const float* __restrict__ Ww0) {
    int t = blockIdx.z;
    int size = (t == 0) ? 2048 : (t == 1) ? 2049 : (t == 2) ? 21 : 4096;
    int base = (t == 0) ? OFF_START : (t == 1) ? OFF_END : (t == 2) ? OFF_LEN : OFF_MID;
    int r0 = blockIdx.x * 16;
    if (r0 >= size) return;
    int woff = 512 + 32 * t;
    int ch = blockIdx.y * 256;
    __shared__ float Ws[32][256];
    __shared__ float pe[16][33];
    int tid = threadIdx.x;
    for (int i = tid; i < 32 * 256; i += 256) {
        int d = i >> 8, c = i & 255;
        Ws[d][c] = Ww0[(size_t)(woff + d) * 512 + ch + c];
    }
    for (int i = tid; i < 16 * 32; i += 256) {
        int rr = i >> 5, d = i & 31, k = d & 15;
        float v = (float)(r0 + rr);
        if (t == 3) v *= 0.5f;
        float freq = expf(-logf(10000.0f) * ((float)(2 * k) / 32.0f));
        float ang = v * freq;
        pe[rr][d] = (d < 16) ? sinf(ang) : cosf(ang);
    }
    __syncthreads();
    int c = tid;
    for (int rr = 0; rr < 16; rr++) {
        int row = r0 + rr;
        if (row >= size) break;
        float s = 0.f;
#pragma unroll
        for (int d = 0; d < 32; d++) s += pe[rr][d] * Ws[d][c];
        g_TposH[(size_t)(base + row) * 512 + ch + c] = __float2half_rn(s);
    }
}

// ---------------- weight prep: smem tile transpose, all 3 weights ----------
__global__ void __launch_bounds__(256) k_prepwT(const float* __restrict__ W1,
                                                const float* __restrict__ Ww0,
                                                const float* __restrict__ W0) {
    __shared__ float ts[3][32][33];
    int n0 = blockIdx.x * 32, k0 = blockIdx.y * 32;
    int tx = threadIdx.x & 31, ty = threadIdx.x >> 5;   // 32 x 8
    for (int i = ty; i < 32; i += 8) {
        ts[0][i][tx] = W1[(size_t)(k0 + i) * 512 + n0 + tx];
        ts[1][i][tx] = Ww0[(size_t)(k0 + i) * 512 + n0 + tx];
        ts[2][i][tx] = W0[(size_t)(k0 + i) * 512 + n0 + tx];
    }
    __syncthreads();
    for (int i = ty; i < 32; i += 8) {
        int n = n0 + i, k = k0 + tx;
        g_w1h[(size_t)n * KP + k] = __float2half_rn(ts[0][tx][i]);
        g_w3h[(size_t)n * KP + k] = __float2half_rn(ts[1][tx][i]);
        __half hi = __float2half_rn(ts[2][tx][i]);
        g_w0h[(size_t)n * KW + k] = hi;
        g_w0h[(size_t)n * KW + 512 + k] = hi;
    }
}

// ---------------- GEMM1: csumW = csumH(fp16x2) @ w0h -> fp32 ---------------
#define W_NKT (KW / 64)        // 16
#define STB   32768
#define NSTG  3
#define SMEM_TOTAL (NSTG * STB)

__global__ void __launch_bounds__(256, 2) k_mmW(int M) {
    extern __shared__ __align__(1024) char smem[];
    uint32_t sb = smem_u32(smem);
    int tid = threadIdx.x, lane = tid & 31, wid = tid >> 5;
    int wm = wid & 3, wn = wid >> 2;
    int mb = blockIdx.y * 128, nb = blockIdx.x * 128;
    int m0 = wm * 32, n0 = wn * 64;

    int lr = tid >> 1, lh = tid & 1;
    const char* gA = (const char*)(g_csumH + (size_t)(mb + lr) * KW) + lh * 64;
    const char* gB = (const char*)(g_w0h + (size_t)(nb + lr) * KW) + lh * 64;
    uint32_t so = (uint32_t)lr * 128 + lh * 64;

    float acc[2][8][4] = {};

#pragma unroll
    for (int s = 0; s < NSTG; s++) {
        uint32_t Ab = sb + s * STB, Bb = Ab + 16384;
        const char* a = gA + s * 128;
        const char* b = gB + s * 128;
#pragma unroll
        for (int i = 0; i < 4; i++) {
            cpa16(Ab + swz(so + i * 16), a + i * 16);
            cpa16(Bb + swz(so + i * 16), b + i * 16);
        }
        asm volatile("cp.async.commit_group;" ::: "memory");
    }

    for (int kt = 0; kt < W_NKT; kt++) {
        asm volatile("cp.async.wait_group 2;" ::: "memory");
        __syncthreads();
        uint32_t Ab = sb + (kt % NSTG) * STB, Bb = Ab + 16384;
        int q = lane >> 3, ro = ((q >> 1) << 3) + (lane & 7), kb = (q & 1) * 16;
#pragma unroll
        for (int k16 = 0; k16 < 4; k16++) {
            uint32_t af[2][4];
#pragma unroll
            for (int mi = 0; mi < 2; mi++) {
                uint32_t addr = Ab + swz((uint32_t)(m0 + mi * 16 + (lane & 15)) * 128 +
                                         k16 * 32 + (lane >> 4) * 16);
                LDMX4(af[mi], addr);
            }
            uint32_t bf[4][4];
#pragma unroll
            for (int nj = 0; nj < 4; nj++) {
                uint32_t addr = Bb + swz((uint32_t)(n0 + nj * 16 + ro) * 128 + k16 * 32 + kb);
                LDMX4(bf[nj], addr);
            }
#pragma unroll
            for (int mi = 0; mi < 2; mi++)
#pragma unroll
                for (int jj = 0; jj < 8; jj++)
                    MMA16816(acc[mi][jj], af[mi], &bf[jj >> 1][(jj & 1) * 2]);
        }
        __syncthreads();
        if (kt + NSTG < W_NKT) {
            uint32_t Ab2 = sb + (kt % NSTG) * STB, Bb2 = Ab2 + 16384;
            const char* a = gA + (kt + NSTG) * 128;
            const char* b = gB + (kt + NSTG) * 128;
#pragma unroll
            for (int i = 0; i < 4; i++) {
                cpa16(Ab2 + swz(so + i * 16), a + i * 16);
                cpa16(Bb2 + swz(so + i * 16), b + i * 16);
            }
        }
        asm volatile("cp.async.commit_group;" ::: "memory");
    }

    int qr = lane >> 2, qc = (lane & 3) * 2;
#pragma unroll
    for (int mi = 0; mi < 2; mi++) {
#pragma unroll
        for (int half = 0; half < 2; half++) {
            int row = mb + m0 + mi * 16 + qr + half * 8;
            if (row >= M) continue;
#pragma unroll
            for (int jj = 0; jj < 8; jj++) {
                int gn = nb + n0 + jj * 8 + qc;
                float2 o = make_float2(acc[mi][jj][half * 2 + 0], acc[mi][jj][half * 2 + 1]);
                *(float2*)(g_csumW + (size_t)row * 512 + gn) = o;
            }
        }
    }
}

// ---------------- buildA grouped by span start ------------------------------
__global__ void __launch_bounds__(128) k_buildA(const float* __restrict__ b0) {
    int i = blockIdx.x;
    int cnt = min(MAXC, NTOK - i);
    int m = i - (NTOK - MAXC - 1);          // i - 2029
    int base = MAXC * i - (m > 0 ? (m * (m + 1)) / 2 : 0);
    int k4 = threadIdx.x;
    float4 s4 = *(const float4*)(g_csumW + (size_t)i * 512 + 4 * k4);
    float4 bb = *(const float4*)(b0 + 4 * k4);
    for (int r = 0; r < cnt; r++) {
        float4 e4 = *(const float4*)(g_csumW + (size_t)(i + r + 1) * 512 + 4 * k4);
        float inv = 1.f / (float)(r + 1);
        float h0 = fmaxf((e4.x - s4.x) * inv + bb.x, 0.f);
        float h1 = fmaxf((e4.y - s4.y) * inv + bb.y, 0.f);
        float h2 = fmaxf((e4.z - s4.z) * inv + bb.z, 0.f);
        float h3 = fmaxf((e4.w - s4.w) * inv + bb.w, 0.f);
        __half2 hh[2];
        hh[0] = __halves2half2(__float2half_rn(h0), __float2half_rn(h1));
        hh[1] = __halves2half2(__float2half_rn(h2), __float2half_rn(h3));
        *(uint2*)(g_hA + (size_t)(base + r) * KP + 4 * k4) = *(uint2*)hh;
    }
}

// ---------------- HMMA fp16 GEMM, CTA tile 128x128, warp tile 32x64 --------
#define KTILE 64
#define NKT   (KP / KTILE)     // 8

template <int WHICH>
__global__ void __launch_bounds__(256, 2) k_mm(const float* __restrict__ bias,
                                               const float* __restrict__ ww1,
                                               const int* __restrict__ sst,
                                               const int* __restrict__ sln, int M) {
    extern __shared__ __align__(1024) char smem[];
    uint32_t sb = smem_u32(smem);
    const __half* A = (WHICH == 2) ? g_hA : g_pA;
    const __half* B = (WHICH == 2) ? g_w1h : g_w3h;
    int tid = threadIdx.x, lane = tid & 31, wid = tid >> 5;
    int wm = wid & 3, wn = wid >> 2;
    int mb = blockIdx.y * 128, nb = blockIdx.x * 128;
    int m0 = wm * 32, n0 = wn * 64;

    int lr = tid >> 1, lh = tid & 1;
    const char* gA = (const char*)(A + (size_t)(mb + lr) * KP) + lh * 64;
    const char* gB = (const char*)(B + (size_t)(nb + lr) * KP) + lh * 64;
    uint32_t so = (uint32_t)lr * 128 + lh * 64;

    float acc[2][8][4] = {};

#pragma unroll
    for (int s = 0; s < NSTG; s++) {
        uint32_t Ab = sb + s * STB, Bb = Ab + 16384;
        const char* a = gA + s * 128;
        const char* b = gB + s * 128;
#pragma unroll
        for (int i = 0; i < 4; i++) {
            cpa16(Ab + swz(so + i * 16), a + i * 16);
            cpa16(Bb + swz(so + i * 16), b + i * 16);
        }
        asm volatile("cp.async.commit_group;" ::: "memory");
    }

    for (int kt = 0; kt < NKT; kt++) {
        asm volatile("cp.async.wait_group 2;" ::: "memory");
        __syncthreads();
        uint32_t Ab = sb + (kt % NSTG) * STB, Bb = Ab + 16384;
        int q = lane >> 3, ro = ((q >> 1) << 3) + (lane & 7), kb = (q & 1) * 16;
#pragma unroll
        for (int k16 = 0; k16 < 4; k16++) {
            uint32_t af[2][4];
#pragma unroll
            for (int mi = 0; mi < 2; mi++) {
                uint32_t addr = Ab + swz((uint32_t)(m0 + mi * 16 + (lane & 15)) * 128 +
                                         k16 * 32 + (lane >> 4) * 16);
                LDMX4(af[mi], addr);
            }
            uint32_t bf[4][4];
#pragma unroll
            for (int nj = 0; nj < 4; nj++) {
                uint32_t addr = Bb + swz((uint32_t)(n0 + nj * 16 + ro) * 128 + k16 * 32 + kb);
                LDMX4(bf[nj], addr);
            }
#pragma unroll
            for (int mi = 0; mi < 2; mi++)
#pragma unroll
                for (int jj = 0; jj < 8; jj++)
                    MMA16816(acc[mi][jj], af[mi], &bf[jj >> 1][(jj & 1) * 2]);
        }
        __syncthreads();
        if (kt + NSTG < NKT) {
            uint32_t Ab2 = sb + (kt % NSTG) * STB, Bb2 = Ab2 + 16384;
            const char* a = gA + (kt + NSTG) * 128;
            const char* b = gB + (kt + NSTG) * 128;
#pragma unroll
            for (int i = 0; i < 4; i++) {
                cpa16(Ab2 + swz(so + i * 16), a + i * 16);
                cpa16(Bb2 + swz(so + i * 16), b + i * 16);
            }
        }
        asm volatile("cp.async.commit_group;" ::: "memory");
    }

    int qr = lane >> 2, qc = (lane & 3) * 2;

    if (WHICH == 2) {
#pragma unroll
        for (int mi = 0; mi < 2; mi++) {
#pragma unroll
            for (int half = 0; half < 2; half++) {
                int row = mb + m0 + mi * 16 + qr + half * 8;
                if (row >= M) continue;
                __half* dst = g_pA + (size_t)row * KP;
#pragma unroll
                for (int jj = 0; jj < 8; jj++) {
                    int gn = nb + n0 + jj * 8 + qc;
                    float2 bb = *(const float2*)(bias + gn);
                    float f0 = fmaxf(acc[mi][jj][half * 2 + 0] + bb.x, 0.f);
                    float f1 = fmaxf(acc[mi][jj][half * 2 + 1] + bb.y, 0.f);
                    *(__half2*)(dst + gn) =
                        __halves2half2(__float2half_rn(f0), __float2half_rn(f1));
                }
            }
        }
    } else {
        float* sred = (float*)smem;
        float dsum[2][2];
#pragma unroll
        for (int mi = 0; mi < 2; mi++) {
#pragma unroll
            for (int half = 0; half < 2; half++) {
                int row = mb + m0 + mi * 16 + qr + half * 8;
                float dot = 0.f;
                if (row < M) {
                    int s = sst[row], l = sln[row];
                    const __half* T0 = g_TposH + (size_t)(OFF_START + s) * 512;
                    const __half* T1 = g_TposH + (size_t)(OFF_END + s + l) * 512;
                    const __half* T2 = g_TposH + (size_t)(OFF_LEN + l) * 512;
                    const __half* T3 = g_TposH + (size_t)(OFF_MID + 2 * s + l) * 512;
#pragma unroll
                    for (int jj = 0; jj < 8; jj++) {
                        int gn = nb + n0 + jj * 8 + qc;
                        float2 t0 = __half22float2(*(const __half2*)(T0 + gn));
                        float2 t1 = __half22float2(*(const __half2*)(T1 + gn));
                        float2 t2 = __half22float2(*(const __half2*)(T2 + gn));
                        float2 t3 = __half22float2(*(const __half2*)(T3 + gn));
                        float2 bb = *(const float2*)(bias + gn);
                        float2 w1 = *(const float2*)(ww1 + gn);
                        float v0 = fmaxf(acc[mi][jj][half * 2 + 0] + bb.x +
                                         t0.x + t1.x + t2.x + t3.x, 0.f);
                        float v1 = fmaxf(acc[mi][jj][half * 2 + 1] + bb.y +
                                         t0.y + t1.y + t2.y + t3.y, 0.f);
                        dot += v0 * w1.x + v1 * w1.y;
                    }
                }
                dot += __shfl_xor_sync(0xffffffff, dot, 1);
                dot += __shfl_xor_sync(0xffffffff, dot, 2);
                dsum[mi][half] = dot;
            }
        }
        __syncthreads();
        if ((lane & 3) == 0) {
#pragma unroll
            for (int mi = 0; mi < 2; mi++)
#pragma unroll
                for (int half = 0; half < 2; half++)
                    sred[wn * 128 + m0 + mi * 16 + qr + half * 8] = dsum[mi][half];
        }
        __syncthreads();
        if (tid < 128) {
            int row = mb + tid;
            if (row < M) g_partial[row * 4 + blockIdx.x] = sred[tid] + sred[128 + tid];
        }
    }
}

// ---------------- final combine ----------------
__global__ void k_final(const float* __restrict__ wb1, float* __restrict__ out, int M) {
    int c = blockIdx.x * 256 + threadIdx.x;
    if (c < M)
        out[c] = g_partial[c * 4 + 0] + g_partial[c * 4 + 1] +
                 g_partial[c * 4 + 2] + g_partial[c * 4 + 3] + wb1[0];
}

// ---------------- launch ----------------
extern "C" void kernel_launch(void* const* d_in, const int* in_sizes, int n_in,
                              void* d_out, int out_size) {
    const int*   sent = (const int*)d_in[0];
    const int*   tags = (const int*)d_in[1];
    const int*   sst  = (const int*)d_in[2];
    const int*   sln  = (const int*)d_in[3];
    const float* Wwrd = (const float*)d_in[4];
    const float* Wpos = (const float*)d_in[5];
    const float* w0   = (const float*)d_in[6];
    const float* b0   = (const float*)d_in[7];
    const float* w1   = (const float*)d_in[8];
    const float* b1   = (const float*)d_in[9];
    const float* ww0  = (const float*)d_in[10];
    const float* wb0  = (const float*)d_in[11];
    const float* ww1  = (const float*)d_in[12];
    const float* wb1  = (const float*)d_in[13];
    float* out = (float*)d_out;
    int M = in_sizes[2];

    cudaFuncSetAttribute(k_mmW, cudaFuncAttributeMaxDynamicSharedMemorySize, SMEM_TOTAL);
    cudaFuncSetAttribute(k_mm<2>, cudaFuncAttributeMaxDynamicSharedMemorySize, SMEM_TOTAL);
    cudaFuncSetAttribute(k_mm<3>, cudaFuncAttributeMaxDynamicSharedMemorySize, SMEM_TOTAL);

    k_segsum<<<dim3(NSEG, 2), 256>>>(sent, tags, Wwrd, Wpos);
    k_segscan<<<1, 512>>>();
    k_csum<<<dim3(NSEG, 2), 256>>>(sent, tags, Wwrd, Wpos);
    k_prepwT<<<dim3(16, 16), 256>>>(w1, ww0, w0);
    k_tables<<<dim3(256, 2, 4), 256>>>(ww0);
    k_mmW<<<dim3(4, (MW + 127) / 128), 256, SMEM_TOTAL>>>(MW);
    k_buildA<<<NTOK, 128>>>(b0);

    int mtiles = (M + 127) / 128;
    k_mm<2><<<dim3(4, mtiles), 256, SMEM_TOTAL>>>(b1, nullptr, nullptr, nullptr, M);
    k_mm<3><<<dim3(4, mtiles), 256, SMEM_TOTAL>>>(wb0, ww1, sst, sln, M);

    k_final<<<(M + 255) / 256, 256>>>(wb1, out, M);
}

// round 16
// speedup vs baseline: 1.0548x; 1.0548x over previous
#include <cuda_runtime.h>
#include <cuda_fp16.h>
#include <cstdint>

// ---------------- problem constants ----------------
#define NTOK   2048
#define EMB    512
#define HD     512
#define NSEG   32
#define SEGLEN 64
#define MAXM   40960
#define MAXC   20
#define KP     512             // pure fp16 for GEMM2/3 (noise cancels; measured)
#define KW     1024            // fp16x2 for GEMM1 (prefix-diff amplification!)
#define MW     2049
#define MWPAD  2176

#define OFF_START 0
#define OFF_END   2048
#define OFF_LEN   4097
#define OFF_MID   4118
#define TROWS     8214

// ---------------- device scratch ----------------
__device__ __half g_csumH[(size_t)MWPAD * KW];
__device__ float g_csumW[(size_t)MW * HD];
__device__ __half g_TposH[(size_t)TROWS * HD];
__device__ float g_segsum[NSEG * EMB];
__device__ float g_segoff[NSEG * EMB];
__device__ float g_partial[MAXM * 4];
__device__ __half g_hA[(size_t)MAXM * KP];
__device__ __half g_pA[(size_t)MAXM * KP];
__device__ __half g_w1h[(size_t)512 * KP];
__device__ __half g_w3h[(size_t)512 * KP];
__device__ __half g_w0h[(size_t)512 * KW];

// ---------------- PTX helpers (plain sm_80+ features only) ----------------
__device__ __forceinline__ uint32_t smem_u32(const void* p) {
    uint32_t a;
    asm("{ .reg .u64 t; cvta.to.shared.u64 t, %1; cvt.u32.u64 %0, t; }" : "=r"(a) : "l"(p));
    return a;
}
__device__ __forceinline__ void cpa16(uint32_t dst, const void* src) {
    asm volatile("cp.async.cg.shared.global [%0], [%1], 16;" :: "r"(dst), "l"(src));
}
__device__ __forceinline__ uint32_t swz(uint32_t o) { return o ^ ((o >> 3) & 0x70); }

#define LDMX4(r, addr) \
    asm volatile("ldmatrix.sync.aligned.m8n8.x4.shared.b16 {%0,%1,%2,%3}, [%4];" \
        : "=r"((r)[0]), "=r"((r)[1]), "=r"((r)[2]), "=r"((r)[3]) : "r"(addr))

#define MMA16816(c, a, b) \
    asm volatile("mma.sync.aligned.m16n8k16.row.col.f32.f16.f16.f32 " \
        "{%0,%1,%2,%3}, {%4,%5,%6,%7}, {%8,%9}, {%0,%1,%2,%3};" \
        : "+f"((c)[0]), "+f"((c)[1]), "+f"((c)[2]), "+f"((c)[3]) \
        : "r"((a)[0]), "r"((a)[1]), "r"((a)[2]), "r"((a)[3]), "r"((b)[0]), "r"((b)[1]))

// ---------------- token prefix sums ----------------
__device__ __forceinline__ float embval(const int* __restrict__ sent,
                                        const int* __restrict__ tags,
                                        const float* __restrict__ Wwrd,
                                        const float* __restrict__ Wpos,
                                        int t, int col) {
    if (col < 256) return Wpos[tags[t] * 256 + col];
    return Wwrd[(size_t)sent[t] * 256 + (col - 256)];
}
__global__ void k_segsum(const int* __restrict__ sent, const int* __restrict__ tags,
                         const float* __restrict__ Wwrd, const float* __restrict__ Wpos) {
    int seg = blockIdx.x;
    int col = blockIdx.y * 256 + threadIdx.x;
    float acc = 0.f;
    int t0 = seg * SEGLEN;
    for (int t = t0; t < t0 + SEGLEN; t++) acc += embval(sent, tags, Wwrd, Wpos, t, col);
    g_segsum[seg * EMB + col] = acc;
}
__global__ void k_segscan() {
    int col = threadIdx.x;
    float run = 0.f;
    for (int s = 0; s < NSEG; s++) {
        float v = g_segsum[s * EMB + col];
        g_segoff[s * EMB + col] = run;
        run += v;
    }
}
__global__ void k_csum(const int* __restrict__ sent, const int* __restrict__ tags,
                       const float* __restrict__ Wwrd, const float* __restrict__ Wpos) {
    int seg = blockIdx.x;
    int col = blockIdx.y * 256 + threadIdx.x;
    float acc = g_segoff[seg * EMB + col];
    if (seg == 0) {
        g_csumH[col] = __float2half_rn(0.f);
        g_csumH[512 + col] = __float2half_rn(0.f);
    }
    int t0 = seg * SEGLEN;
    for (int t = t0; t < t0 + SEGLEN; t++) {
        acc += embval(sent, tags, Wwrd, Wpos, t, col);
        __half hi = __float2half_rn(acc);
        __half lo = __float2half_rn(acc - __half2float(hi));
        g_csumH[(size_t)(t + 1) * KW + col] = hi;
        g_csumH[(size_t)(t + 1) * KW + 512 + col] = lo;
    }
}

// ---------------- positional tables: weights in REGISTERS, pe via smem -----
// grid (64, 2, 4): z = table, x = 64-row group, y = 256-col half.
// Thread owns one column; its 32 weights live in registers (loaded once).
__global__ void __launch_bounds__(256) k_tables(const float* __restrict__ Ww0) {
    int t = blockIdx.z;
    int size = (t == 0) ? 2048 : (t == 1) ? 2049 : (t == 2) ? 21 : 4096;
    int base = (t == 0) ? OFF_START : (t == 1) ? OFF_END : (t == 2) ? OFF_LEN : OFF_MID;
    int r0 = blockIdx.x * 64;
    if (r0 >= size) return;
    int woff = 512 + 32 * t;
    int ch = blockIdx.y * 256;
    int c = threadIdx.x;

    float wreg[32];
#pragma unroll
    for (int d = 0; d < 32; d++) wreg[d] = Ww0[(size_t)(woff + d) * 512 + ch + c];

    __shared__ float pe[64][32];
    for (int i = c; i < 64 * 32; i += 256) {
        int rr = i >> 5, d = i & 31, k = d & 15;
        float v = (float)(r0 + rr);
        if (t == 3) v *= 0.5f;
        float freq = expf(-logf(10000.0f) * ((float)(2 * k) / 32.0f));
        float ang = v * freq;
        pe[rr][d] = (d < 16) ? sinf(ang) : cosf(ang);
    }
    __syncthreads();

    int cnt = min(64, size - r0);
    for (int rr = 0; rr < cnt; rr++) {
        const float4* p4 = (const float4*)pe[rr];
        float s = 0.f;
#pragma unroll
        for (int q = 0; q < 8; q++) {
            float4 p = p4[q];
            s += p.x * wreg[4 * q + 0] + p.y * wreg[4 * q + 1] +
                 p.z * wreg[4 * q + 2] + p.w * wreg[4 * q + 3];
        }
        g_TposH[(size_t)(base + r0 + rr) * 512 + ch + c] = __float2half_rn(s);
    }
}

// ---------------- weight prep: smem tile transpose, all 3 weights ----------
__global__ void __launch_bounds__(256) k_prepwT(const float* __restrict__ W1,
                                                const float* __restrict__ Ww0,
                                                const float* __restrict__ W0) {
    __shared__ float ts[3][32][33];
    int n0 = blockIdx.x * 32, k0 = blockIdx.y * 32;
    int tx = threadIdx.x & 31, ty = threadIdx.x >> 5;   // 32 x 8
    for (int i = ty; i < 32; i += 8) {
        ts[0][i][tx] = W1[(size_t)(k0 + i) * 512 + n0 + tx];
        ts[1][i][tx] = Ww0[(size_t)(k0 + i) * 512 + n0 + tx];
        ts[2][i][tx] = W0[(size_t)(k0 + i) * 512 + n0 + tx];
    }
    __syncthreads();
    for (int i = ty; i < 32; i += 8) {
        int n = n0 + i, k = k0 + tx;
        g_w1h[(size_t)n * KP + k] = __float2half_rn(ts[0][tx][i]);
        g_w3h[(size_t)n * KP + k] = __float2half_rn(ts[1][tx][i]);
        __half hi = __float2half_rn(ts[2][tx][i]);
        g_w0h[(size_t)n * KW + k] = hi;
        g_w0h[(size_t)n * KW + 512 + k] = hi;
    }
}

// ---------------- GEMM1: csumW = csumH(fp16x2) @ w0h -> fp32 ---------------
#define W_NKT (KW / 64)        // 16
#define STB   32768
#define NSTG  3
#define SMEM_TOTAL (NSTG * STB)

__global__ void __launch_bounds__(256, 2) k_mmW(int M) {
    extern __shared__ __align__(1024) char smem[];
    uint32_t sb = smem_u32(smem);
    int tid = threadIdx.x, lane = tid & 31, wid = tid >> 5;
    int wm = wid & 3, wn = wid >> 2;
    int mb = blockIdx.y * 128, nb = blockIdx.x * 128;
    int m0 = wm * 32, n0 = wn * 64;

    int lr = tid >> 1, lh = tid & 1;
    const char* gA = (const char*)(g_csumH + (size_t)(mb + lr) * KW) + lh * 64;
    const char* gB = (const char*)(g_w0h + (size_t)(nb + lr) * KW) + lh * 64;
    uint32_t so = (uint32_t)lr * 128 + lh * 64;

    float acc[2][8][4] = {};

#pragma unroll
    for (int s = 0; s < NSTG; s++) {
        uint32_t Ab = sb + s * STB, Bb = Ab + 16384;
        const char* a = gA + s * 128;
        const char* b = gB + s * 128;
#pragma unroll
        for (int i = 0; i < 4; i++) {
            cpa16(Ab + swz(so + i * 16), a + i * 16);
            cpa16(Bb + swz(so + i * 16), b + i * 16);
        }
        asm volatile("cp.async.commit_group;" ::: "memory");
    }

    for (int kt = 0; kt < W_NKT; kt++) {
        asm volatile("cp.async.wait_group 2;" ::: "memory");
        __syncthreads();
        uint32_t Ab = sb + (kt % NSTG) * STB, Bb = Ab + 16384;
        int q = lane >> 3, ro = ((q >> 1) << 3) + (lane & 7), kb = (q & 1) * 16;
#pragma unroll
        for (int k16 = 0; k16 < 4; k16++) {
            uint32_t af[2][4];
#pragma unroll
            for (int mi = 0; mi < 2; mi++) {
                uint32_t addr = Ab + swz((uint32_t)(m0 + mi * 16 + (lane & 15)) * 128 +
                                         k16 * 32 + (lane >> 4) * 16);
                LDMX4(af[mi], addr);
            }
            uint32_t bf[4][4];
#pragma unroll
            for (int nj = 0; nj < 4; nj++) {
                uint32_t addr = Bb + swz((uint32_t)(n0 + nj * 16 + ro) * 128 + k16 * 32 + kb);
                LDMX4(bf[nj], addr);
            }
#pragma unroll
            for (int mi = 0; mi < 2; mi++)
#pragma unroll
                for (int jj = 0; jj < 8; jj++)
                    MMA16816(acc[mi][jj], af[mi], &bf[jj >> 1][(jj & 1) * 2]);
        }
        __syncthreads();
        if (kt + NSTG < W_NKT) {
            uint32_t Ab2 = sb + (kt % NSTG) * STB, Bb2 = Ab2 + 16384;
            const char* a = gA + (kt + NSTG) * 128;
            const char* b = gB + (kt + NSTG) * 128;
#pragma unroll
            for (int i = 0; i < 4; i++) {
                cpa16(Ab2 + swz(so + i * 16), a + i * 16);
                cpa16(Bb2 + swz(so + i * 16), b + i * 16);
            }
        }
        asm volatile("cp.async.commit_group;" ::: "memory");
    }

    int qr = lane >> 2, qc = (lane & 3) * 2;
#pragma unroll
    for (int mi = 0; mi < 2; mi++) {
#pragma unroll
        for (int half = 0; half < 2; half++) {
            int row = mb + m0 + mi * 16 + qr + half * 8;
            if (row >= M) continue;
#pragma unroll
            for (int jj = 0; jj < 8; jj++) {
                int gn = nb + n0 + jj * 8 + qc;
                float2 o = make_float2(acc[mi][jj][half * 2 + 0], acc[mi][jj][half * 2 + 1]);
                *(float2*)(g_csumW + (size_t)row * 512 + gn) = o;
            }
        }
    }
}

// ---------------- buildA grouped by span start ------------------------------
__global__ void __launch_bounds__(128) k_buildA(const float* __restrict__ b0) {
    int i = blockIdx.x;
    int cnt = min(MAXC, NTOK - i);
    int m = i - (NTOK - MAXC - 1);          // i - 2029
    int base = MAXC * i - (m > 0 ? (m * (m + 1)) / 2 : 0);
    int k4 = threadIdx.x;
    float4 s4 = *(const float4*)(g_csumW + (size_t)i * 512 + 4 * k4);
    float4 bb = *(const float4*)(b0 + 4 * k4);
    for (int r = 0; r < cnt; r++) {
        float4 e4 = *(const float4*)(g_csumW + (size_t)(i + r + 1) * 512 + 4 * k4);
        float inv = 1.f / (float)(r + 1);
        float h0 = fmaxf((e4.x - s4.x) * inv + bb.x, 0.f);
        float h1 = fmaxf((e4.y - s4.y) * inv + bb.y, 0.f);
        float h2 = fmaxf((e4.z - s4.z) * inv + bb.z, 0.f);
        float h3 = fmaxf((e4.w - s4.w) * inv + bb.w, 0.f);
        __half2 hh[2];
        hh[0] = __halves2half2(__float2half_rn(h0), __float2half_rn(h1));
        hh[1] = __halves2half2(__float2half_rn(h2), __float2half_rn(h3));
        *(uint2*)(g_hA + (size_t)(base + r) * KP + 4 * k4) = *(uint2*)hh;
    }
}

// ---------------- HMMA fp16 GEMM, CTA tile 128x128, warp tile 32x64 --------
#define KTILE 64
#define NKT   (KP / KTILE)     // 8

template <int WHICH>
__global__ void __launch_bounds__(256, 2) k_mm(const float* __restrict__ bias,
                                               const float* __restrict__ ww1,
                                               const int* __restrict__ sst,
                                               const int* __restrict__ sln, int M) {
    extern __shared__ __align__(1024) char smem[];
    uint32_t sb = smem_u32(smem);
    const __half* A = (WHICH == 2) ? g_hA : g_pA;
    const __half* B = (WHICH == 2) ? g_w1h : g_w3h;
    int tid = threadIdx.x, lane = tid & 31, wid = tid >> 5;
    int wm = wid & 3, wn = wid >> 2;
    int mb = blockIdx.y * 128, nb = blockIdx.x * 128;
    int m0 = wm * 32, n0 = wn * 64;

    int lr = tid >> 1, lh = tid & 1;
    const char* gA = (const char*)(A + (size_t)(mb + lr) * KP) + lh * 64;
    const char* gB = (const char*)(B + (size_t)(nb + lr) * KP) + lh * 64;
    uint32_t so = (uint32_t)lr * 128 + lh * 64;

    float acc[2][8][4] = {};

#pragma unroll
    for (int s = 0; s < NSTG; s++) {
        uint32_t Ab = sb + s * STB, Bb = Ab + 16384;
        const char* a = gA + s * 128;
        const char* b = gB + s * 128;
#pragma unroll
        for (int i = 0; i < 4; i++) {
            cpa16(Ab + swz(so + i * 16), a + i * 16);
            cpa16(Bb + swz(so + i * 16), b + i * 16);
        }
        asm volatile("cp.async.commit_group;" ::: "memory");
    }

    for (int kt = 0; kt < NKT; kt++) {
        asm volatile("cp.async.wait_group 2;" ::: "memory");
        __syncthreads();
        uint32_t Ab = sb + (kt % NSTG) * STB, Bb = Ab + 16384;
        int q = lane >> 3, ro = ((q >> 1) << 3) + (lane & 7), kb = (q & 1) * 16;
#pragma unroll
        for (int k16 = 0; k16 < 4; k16++) {
            uint32_t af[2][4];
#pragma unroll
            for (int mi = 0; mi < 2; mi++) {
                uint32_t addr = Ab + swz((uint32_t)(m0 + mi * 16 + (lane & 15)) * 128 +
                                         k16 * 32 + (lane >> 4) * 16);
                LDMX4(af[mi], addr);
            }
            uint32_t bf[4][4];
#pragma unroll
            for (int nj = 0; nj < 4; nj++) {
                uint32_t addr = Bb + swz((uint32_t)(n0 + nj * 16 + ro) * 128 + k16 * 32 + kb);
                LDMX4(bf[nj], addr);
            }
#pragma unroll
            for (int mi = 0; mi < 2; mi++)
#pragma unroll
                for (int jj = 0; jj < 8; jj++)
                    MMA16816(acc[mi][jj], af[mi], &bf[jj >> 1][(jj & 1) * 2]);
        }
        __syncthreads();
        if (kt + NSTG < NKT) {
            uint32_t Ab2 = sb + (kt % NSTG) * STB, Bb2 = Ab2 + 16384;
            const char* a = gA + (kt + NSTG) * 128;
            const char* b = gB + (kt + NSTG) * 128;
#pragma unroll
            for (int i = 0; i < 4; i++) {
                cpa16(Ab2 + swz(so + i * 16), a + i * 16);
                cpa16(Bb2 + swz(so + i * 16), b + i * 16);
            }
        }
        asm volatile("cp.async.commit_group;" ::: "memory");
    }

    int qr = lane >> 2, qc = (lane & 3) * 2;

    if (WHICH == 2) {
#pragma unroll
        for (int mi = 0; mi < 2; mi++) {
#pragma unroll
            for (int half = 0; half < 2; half++) {
                int row = mb + m0 + mi * 16 + qr + half * 8;
                if (row >= M) continue;
                __half* dst = g_pA + (size_t)row * KP;
#pragma unroll
                for (int jj = 0; jj < 8; jj++) {
                    int gn = nb + n0 + jj * 8 + qc;
                    float2 bb = *(const float2*)(bias + gn);
                    float f0 = fmaxf(acc[mi][jj][half * 2 + 0] + bb.x, 0.f);
                    float f1 = fmaxf(acc[mi][jj][half * 2 + 1] + bb.y, 0.f);
                    *(__half2*)(dst + gn) =
                        __halves2half2(__float2half_rn(f0), __float2half_rn(f1));
                }
            }
        }
    } else {
        float* sred = (float*)smem;
        float dsum[2][2];
#pragma unroll
        for (int mi = 0; mi < 2; mi++) {
#pragma unroll
            for (int half = 0; half < 2; half++) {
                int row = mb + m0 + mi * 16 + qr + half * 8;
                float dot = 0.f;
                if (row < M) {
                    int s = sst[row], l = sln[row];
                    const __half* T0 = g_TposH + (size_t)(OFF_START + s) * 512;
                    const __half* T1 = g_TposH + (size_t)(OFF_END + s + l) * 512;
                    const __half* T2 = g_TposH + (size_t)(OFF_LEN + l) * 512;
                    const __half* T3 = g_TposH + (size_t)(OFF_MID + 2 * s + l) * 512;
#pragma unroll
                    for (int jj = 0; jj < 8; jj++) {
                        int gn = nb + n0 + jj * 8 + qc;
                        float2 t0 = __half22float2(*(const __half2*)(T0 + gn));
                        float2 t1 = __half22float2(*(const __half2*)(T1 + gn));
                        float2 t2 = __half22float2(*(const __half2*)(T2 + gn));
                        float2 t3 = __half22float2(*(const __half2*)(T3 + gn));
                        float2 bb = *(const float2*)(bias + gn);
                        float2 w1 = *(const float2*)(ww1 + gn);
                        float v0 = fmaxf(acc[mi][jj][half * 2 + 0] + bb.x +
                                         t0.x + t1.x + t2.x + t3.x, 0.f);
                        float v1 = fmaxf(acc[mi][jj][half * 2 + 1] + bb.y +
                                         t0.y + t1.y + t2.y + t3.y, 0.f);
                        dot += v0 * w1.x + v1 * w1.y;
                    }
                }
                dot += __shfl_xor_sync(0xffffffff, dot, 1);
                dot += __shfl_xor_sync(0xffffffff, dot, 2);
                dsum[mi][half] = dot;
            }
        }
        __syncthreads();
        if ((lane & 3) == 0) {
#pragma unroll
            for (int mi = 0; mi < 2; mi++)
#pragma unroll
                for (int half = 0; half < 2; half++)
                    sred[wn * 128 + m0 + mi * 16 + qr + half * 8] = dsum[mi][half];
        }
        __syncthreads();
        if (tid < 128) {
            int row = mb + tid;
            if (row < M) g_partial[row * 4 + blockIdx.x] = sred[tid] + sred[128 + tid];
        }
    }
}

// ---------------- final combine ----------------
__global__ void k_final(const float* __restrict__ wb1, float* __restrict__ out, int M) {
    int c = blockIdx.x * 256 + threadIdx.x;
    if (c < M)
        out[c] = g_partial[c * 4 + 0] + g_partial[c * 4 + 1] +
                 g_partial[c * 4 + 2] + g_partial[c * 4 + 3] + wb1[0];
}

// ---------------- launch ----------------
extern "C" void kernel_launch(void* const* d_in, const int* in_sizes, int n_in,
                              void* d_out, int out_size) {
    const int*   sent = (const int*)d_in[0];
    const int*   tags = (const int*)d_in[1];
    const int*   sst  = (const int*)d_in[2];
    const int*   sln  = (const int*)d_in[3];
    const float* Wwrd = (const float*)d_in[4];
    const float* Wpos = (const float*)d_in[5];
    const float* w0   = (const float*)d_in[6];
    const float* b0   = (const float*)d_in[7];
    const float* w1   = (const float*)d_in[8];
    const float* b1   = (const float*)d_in[9];
    const float* ww0  = (const float*)d_in[10];
    const float* wb0  = (const float*)d_in[11];
    const float* ww1  = (const float*)d_in[12];
    const float* wb1  = (const float*)d_in[13];
    float* out = (float*)d_out;
    int M = in_sizes[2];

    cudaFuncSetAttribute(k_mmW, cudaFuncAttributeMaxDynamicSharedMemorySize, SMEM_TOTAL);
    cudaFuncSetAttribute(k_mm<2>, cudaFuncAttributeMaxDynamicSharedMemorySize, SMEM_TOTAL);
    cudaFuncSetAttribute(k_mm<3>, cudaFuncAttributeMaxDynamicSharedMemorySize, SMEM_TOTAL);

    k_segsum<<<dim3(NSEG, 2), 256>>>(sent, tags, Wwrd, Wpos);
    k_segscan<<<1, 512>>>();
    k_csum<<<dim3(NSEG, 2), 256>>>(sent, tags, Wwrd, Wpos);
    k_prepwT<<<dim3(16, 16), 256>>>(w1, ww0, w0);
    k_tables<<<dim3(64, 2, 4), 256>>>(ww0);
    k_mmW<<<dim3(4, (MW + 127) / 128), 256, SMEM_TOTAL>>>(MW);
    k_buildA<<<NTOK, 128>>>(b0);

    int mtiles = (M + 127) / 128;
    k_mm<2><<<dim3(4, mtiles), 256, SMEM_TOTAL>>>(b1, nullptr, nullptr, nullptr, M);
    k_mm<3><<<dim3(4, mtiles), 256, SMEM_TOTAL>>>(wb0, ww1, sst, sln, M);

    k_final<<<(M + 255) / 256, 256>>>(wb1, out, M);
}

// round 17
// speedup vs baseline: 1.0911x; 1.0344x over previous
#include <cuda_runtime.h>
#include <cuda_fp16.h>
#include <cstdint>

// ---------------- problem constants ----------------
#define NTOK   2048
#define EMB    512
#define HD     512
#define NSEG   128
#define SEGLEN 16
#define MAXM   40960
#define MAXC   20
#define KP     512             // pure fp16 for GEMM2/3 (noise cancels; measured)
#define KW     1024            // fp16x2 for GEMM1 (prefix-diff amplification!)
#define MW     2049
#define MWPAD  2176

#define OFF_START 0
#define OFF_END   2048
#define OFF_LEN   4097
#define OFF_MID   4118
#define TROWS     8214

// ---------------- device scratch ----------------
__device__ __half g_csumH[(size_t)MWPAD * KW];
__device__ float g_csumW[2][(size_t)MW * HD];      // split-K halves of GEMM1
__device__ __half g_TposH[(size_t)TROWS * HD];
__device__ float g_segsum[NSEG * EMB];
__device__ float g_segoff[NSEG * EMB];
__device__ float g_partial[MAXM * 4];
__device__ __half g_hA[(size_t)MAXM * KP];
__device__ __half g_pA[(size_t)MAXM * KP];
__device__ __half g_w1h[(size_t)512 * KP];
__device__ __half g_w3h[(size_t)512 * KP];
__device__ __half g_w0h[(size_t)512 * KW];

// ---------------- PTX helpers (plain sm_80+ features only) ----------------
__device__ __forceinline__ uint32_t smem_u32(const void* p) {
    uint32_t a;
    asm("{ .reg .u64 t; cvta.to.shared.u64 t, %1; cvt.u32.u64 %0, t; }" : "=r"(a) : "l"(p));
    return a;
}
__device__ __forceinline__ void cpa16(uint32_t dst, const void* src) {
    asm volatile("cp.async.cg.shared.global [%0], [%1], 16;" :: "r"(dst), "l"(src));
}
__device__ __forceinline__ uint32_t swz(uint32_t o) { return o ^ ((o >> 3) & 0x70); }

#define LDMX4(r, addr) \
    asm volatile("ldmatrix.sync.aligned.m8n8.x4.shared.b16 {%0,%1,%2,%3}, [%4];" \
        : "=r"((r)[0]), "=r"((r)[1]), "=r"((r)[2]), "=r"((r)[3]) : "r"(addr))

#define MMA16816(c, a, b) \
    asm volatile("mma.sync.aligned.m16n8k16.row.col.f32.f16.f16.f32 " \
        "{%0,%1,%2,%3}, {%4,%5,%6,%7}, {%8,%9}, {%0,%1,%2,%3};" \
        : "+f"((c)[0]), "+f"((c)[1]), "+f"((c)[2]), "+f"((c)[3]) \
        : "r"((a)[0]), "r"((a)[1]), "r"((a)[2]), "r"((a)[3]), "r"((b)[0]), "r"((b)[1]))

// ---------------- token prefix sums ----------------
__device__ __forceinline__ float embval(const int* __restrict__ sent,
                                        const int* __restrict__ tags,
                                        const float* __restrict__ Wwrd,
                                        const float* __restrict__ Wpos,
                                        int t, int col) {
    if (col < 256) return Wpos[tags[t] * 256 + col];
    return Wwrd[(size_t)sent[t] * 256 + (col - 256)];
}
__global__ void k_segsum(const int* __restrict__ sent, const int* __restrict__ tags,
                         const float* __restrict__ Wwrd, const float* __restrict__ Wpos) {
    int seg = blockIdx.x;
    int col = blockIdx.y * 256 + threadIdx.x;
    float acc = 0.f;
    int t0 = seg * SEGLEN;
    for (int t = t0; t < t0 + SEGLEN; t++) acc += embval(sent, tags, Wwrd, Wpos, t, col);
    g_segsum[seg * EMB + col] = acc;
}
__global__ void k_segscan() {
    int col = threadIdx.x;
    float run = 0.f;
    for (int s = 0; s < NSEG; s++) {
        float v = g_segsum[s * EMB + col];
        g_segoff[s * EMB + col] = run;
        run += v;
    }
}
__global__ void k_csum(const int* __restrict__ sent, const int* __restrict__ tags,
                       const float* __restrict__ Wwrd, const float* __restrict__ Wpos) {
    int seg = blockIdx.x;
    int col = blockIdx.y * 256 + threadIdx.x;
    float acc = g_segoff[seg * EMB + col];
    if (seg == 0) {
        g_csumH[col] = __float2half_rn(0.f);
        g_csumH[512 + col] = __float2half_rn(0.f);
    }
    int t0 = seg * SEGLEN;
    for (int t = t0; t < t0 + SEGLEN; t++) {
        acc += embval(sent, tags, Wwrd, Wpos, t, col);
        __half hi = __float2half_rn(acc);
        __half lo = __float2half_rn(acc - __half2float(hi));
        g_csumH[(size_t)(t + 1) * KW + col] = hi;
        g_csumH[(size_t)(t + 1) * KW + 512 + col] = lo;
    }
}

// ---------------- positional tables: weights in registers ----------
__global__ void __launch_bounds__(256) k_tables(const float* __restrict__ Ww0) {
    int t = blockIdx.z;
    int size = (t == 0) ? 2048 : (t == 1) ? 2049 : (t == 2) ? 21 : 4096;
    int base = (t == 0) ? OFF_START : (t == 1) ? OFF_END : (t == 2) ? OFF_LEN : OFF_MID;
    int r0 = blockIdx.x * 64;
    if (r0 >= size) return;
    int woff = 512 + 32 * t;
    int ch = blockIdx.y * 256;
    int c = threadIdx.x;

    float wreg[32];
#pragma unroll
    for (int d = 0; d < 32; d++) wreg[d] = Ww0[(size_t)(woff + d) * 512 + ch + c];

    __shared__ float pe[64][32];
    for (int i = c; i < 64 * 32; i += 256) {
        int rr = i >> 5, d = i & 31, k = d & 15;
        float v = (float)(r0 + rr);
        if (t == 3) v *= 0.5f;
        float freq = expf(-logf(10000.0f) * ((float)(2 * k) / 32.0f));
        float ang = v * freq;
        pe[rr][d] = (d < 16) ? sinf(ang) : cosf(ang);
    }
    __syncthreads();

    int cnt = min(64, size - r0);
    for (int rr = 0; rr < cnt; rr++) {
        const float4* p4 = (const float4*)pe[rr];
        float s = 0.f;
#pragma unroll
        for (int q = 0; q < 8; q++) {
            float4 p = p4[q];
            s += p.x * wreg[4 * q + 0] + p.y * wreg[4 * q + 1] +
                 p.z * wreg[4 * q + 2] + p.w * wreg[4 * q + 3];
        }
        g_TposH[(size_t)(base + r0 + rr) * 512 + ch + c] = __float2half_rn(s);
    }
}

// ---------------- weight prep: smem tile transpose, all 3 weights ----------
__global__ void __launch_bounds__(256) k_prepwT(const float* __restrict__ W1,
                                                const float* __restrict__ Ww0,
                                                const float* __restrict__ W0) {
    __shared__ float ts[3][32][33];
    int n0 = blockIdx.x * 32, k0 = blockIdx.y * 32;
    int tx = threadIdx.x & 31, ty = threadIdx.x >> 5;   // 32 x 8
    for (int i = ty; i < 32; i += 8) {
        ts[0][i][tx] = W1[(size_t)(k0 + i) * 512 + n0 + tx];
        ts[1][i][tx] = Ww0[(size_t)(k0 + i) * 512 + n0 + tx];
        ts[2][i][tx] = W0[(size_t)(k0 + i) * 512 + n0 + tx];
    }
    __syncthreads();
    for (int i = ty; i < 32; i += 8) {
        int n = n0 + i, k = k0 + tx;
        g_w1h[(size_t)n * KP + k] = __float2half_rn(ts[0][tx][i]);
        g_w3h[(size_t)n * KP + k] = __float2half_rn(ts[1][tx][i]);
        __half hi = __float2half_rn(ts[2][tx][i]);
        g_w0h[(size_t)n * KW + k] = hi;
        g_w0h[(size_t)n * KW + 512 + k] = hi;
    }
}

// ---------------- GEMM1: csumW = csumH(fp16x2) @ w0h, split-K=2 ------------
#define W_NKT 8                // 8 k-tiles per split half
#define STB   32768
#define NSTG  3
#define SMEM_TOTAL (NSTG * STB)

__global__ void __launch_bounds__(256, 2) k_mmW(int M) {
    extern __shared__ __align__(1024) char smem[];
    uint32_t sb = smem_u32(smem);
    int tid = threadIdx.x, lane = tid & 31, wid = tid >> 5;
    int wm = wid & 3, wn = wid >> 2;
    int mb = blockIdx.y * 128, nb = blockIdx.x * 128;
    int m0 = wm * 32, n0 = wn * 64;
    int kbase = blockIdx.z * 1024;   // byte offset into KW (512 fp16 = 1024 B)

    int lr = tid >> 1, lh = tid & 1;
    const char* gA = (const char*)(g_csumH + (size_t)(mb + lr) * KW) + kbase + lh * 64;
    const char* gB = (const char*)(g_w0h + (size_t)(nb + lr) * KW) + kbase + lh * 64;
    uint32_t so = (uint32_t)lr * 128 + lh * 64;

    float acc[2][8][4] = {};

#pragma unroll
    for (int s = 0; s < NSTG; s++) {
        uint32_t Ab = sb + s * STB, Bb = Ab + 16384;
        const char* a = gA + s * 128;
        const char* b = gB + s * 128;
#pragma unroll
        for (int i = 0; i < 4; i++) {
            cpa16(Ab + swz(so + i * 16), a + i * 16);
            cpa16(Bb + swz(so + i * 16), b + i * 16);
        }
        asm volatile("cp.async.commit_group;" ::: "memory");
    }

    for (int kt = 0; kt < W_NKT; kt++) {
        asm volatile("cp.async.wait_group 2;" ::: "memory");
        __syncthreads();
        uint32_t Ab = sb + (kt % NSTG) * STB, Bb = Ab + 16384;
        int q = lane >> 3, ro = ((q >> 1) << 3) + (lane & 7), kb = (q & 1) * 16;
#pragma unroll
        for (int k16 = 0; k16 < 4; k16++) {
            uint32_t af[2][4];
#pragma unroll
            for (int mi = 0; mi < 2; mi++) {
                uint32_t addr = Ab + swz((uint32_t)(m0 + mi * 16 + (lane & 15)) * 128 +
                                         k16 * 32 + (lane >> 4) * 16);
                LDMX4(af[mi], addr);
            }
            uint32_t bf[4][4];
#pragma unroll
            for (int nj = 0; nj < 4; nj++) {
                uint32_t addr = Bb + swz((uint32_t)(n0 + nj * 16 + ro) * 128 + k16 * 32 + kb);
                LDMX4(bf[nj], addr);
            }
#pragma unroll
            for (int mi = 0; mi < 2; mi++)
#pragma unroll
                for (int jj = 0; jj < 8; jj++)
                    MMA16816(acc[mi][jj], af[mi], &bf[jj >> 1][(jj & 1) * 2]);
        }
        __syncthreads();
        if (kt + NSTG < W_NKT) {
            uint32_t Ab2 = sb + (kt % NSTG) * STB, Bb2 = Ab2 + 16384;
            const char* a = gA + (kt + NSTG) * 128;
            const char* b = gB + (kt + NSTG) * 128;
#pragma unroll
            for (int i = 0; i < 4; i++) {
                cpa16(Ab2 + swz(so + i * 16), a + i * 16);
                cpa16(Bb2 + swz(so + i * 16), b + i * 16);
            }
        }
        asm volatile("cp.async.commit_group;" ::: "memory");
    }

    int qr = lane >> 2, qc = (lane & 3) * 2;
    float* dst = &g_csumW[blockIdx.z][0];
#pragma unroll
    for (int mi = 0; mi < 2; mi++) {
#pragma unroll
        for (int half = 0; half < 2; half++) {
            int row = mb + m0 + mi * 16 + qr + half * 8;
            if (row >= M) continue;
#pragma unroll
            for (int jj = 0; jj < 8; jj++) {
                int gn = nb + n0 + jj * 8 + qc;
                float2 o = make_float2(acc[mi][jj][half * 2 + 0], acc[mi][jj][half * 2 + 1]);
                *(float2*)(dst + (size_t)row * 512 + gn) = o;
            }
        }
    }
}

// ---------------- buildA grouped by span start, row-split -------------------
// block (i, z): rows r in [10z, min(cnt,10z+10)); csumW row i read once.
__global__ void __launch_bounds__(128) k_buildA(const float* __restrict__ b0) {
    int i = blockIdx.x;
    int cnt = min(MAXC, NTOK - i);
    int rlo = blockIdx.y * 10;
    if (rlo >= cnt) return;
    int rhi = min(cnt, rlo + 10);
    int m = i - (NTOK - MAXC - 1);          // i - 2029
    int base = MAXC * i - (m > 0 ? (m * (m + 1)) / 2 : 0);
    int k4 = threadIdx.x;
    float4 sa = *(const float4*)(&g_csumW[0][0] + (size_t)i * 512 + 4 * k4);
    float4 sb2 = *(const float4*)(&g_csumW[1][0] + (size_t)i * 512 + 4 * k4);
    float4 bb = *(const float4*)(b0 + 4 * k4);
    float s0 = sa.x + sb2.x, s1 = sa.y + sb2.y, s2 = sa.z + sb2.z, s3 = sa.w + sb2.w;
    for (int r = rlo; r < rhi; r++) {
        float4 ea = *(const float4*)(&g_csumW[0][0] + (size_t)(i + r + 1) * 512 + 4 * k4);
        float4 eb = *(const float4*)(&g_csumW[1][0] + (size_t)(i + r + 1) * 512 + 4 * k4);
        float inv = 1.f / (float)(r + 1);
        float h0 = fmaxf(((ea.x + eb.x) - s0) * inv + bb.x, 0.f);
        float h1 = fmaxf(((ea.y + eb.y) - s1) * inv + bb.y, 0.f);
        float h2 = fmaxf(((ea.z + eb.z) - s2) * inv + bb.z, 0.f);
        float h3 = fmaxf(((ea.w + eb.w) - s3) * inv + bb.w, 0.f);
        __half2 hh[2];
        hh[0] = __halves2half2(__float2half_rn(h0), __float2half_rn(h1));
        hh[1] = __halves2half2(__float2half_rn(h2), __float2half_rn(h3));
        *(uint2*)(g_hA + (size_t)(base + r) * KP + 4 * k4) = *(uint2*)hh;
    }
}

// ---------------- HMMA fp16 GEMM, CTA tile 128x128, warp tile 32x64 --------
#define KTILE 64
#define NKT   (KP / KTILE)     // 8

template <int WHICH>
__global__ void __launch_bounds__(256, 2) k_mm(const float* __restrict__ bias,
                                               const float* __restrict__ ww1,
                                               const int* __restrict__ sst,
                                               const int* __restrict__ sln, int M) {
    extern __shared__ __align__(1024) char smem[];
    uint32_t sb = smem_u32(smem);
    const __half* A = (WHICH == 2) ? g_hA : g_pA;
    const __half* B = (WHICH == 2) ? g_w1h : g_w3h;
    int tid = threadIdx.x, lane = tid & 31, wid = tid >> 5;
    int wm = wid & 3, wn = wid >> 2;
    int mb = blockIdx.y * 128, nb = blockIdx.x * 128;
    int m0 = wm * 32, n0 = wn * 64;

    int lr = tid >> 1, lh = tid & 1;
    const char* gA = (const char*)(A + (size_t)(mb + lr) * KP) + lh * 64;
    const char* gB = (const char*)(B + (size_t)(nb + lr) * KP) + lh * 64;
    uint32_t so = (uint32_t)lr * 128 + lh * 64;

    float acc[2][8][4] = {};

#pragma unroll
    for (int s = 0; s < NSTG; s++) {
        uint32_t Ab = sb + s * STB, Bb = Ab + 16384;
        const char* a = gA + s * 128;
        const char* b = gB + s * 128;
#pragma unroll
        for (int i = 0; i < 4; i++) {
            cpa16(Ab + swz(so + i * 16), a + i * 16);
            cpa16(Bb + swz(so + i * 16), b + i * 16);
        }
        asm volatile("cp.async.commit_group;" ::: "memory");
    }

    for (int kt = 0; kt < NKT; kt++) {
        asm volatile("cp.async.wait_group 2;" ::: "memory");
        __syncthreads();
        uint32_t Ab = sb + (kt % NSTG) * STB, Bb = Ab + 16384;
        int q = lane >> 3, ro = ((q >> 1) << 3) + (lane & 7), kb = (q & 1) * 16;
#pragma unroll
        for (int k16 = 0; k16 < 4; k16++) {
            uint32_t af[2][4];
#pragma unroll
            for (int mi = 0; mi < 2; mi++) {
                uint32_t addr = Ab + swz((uint32_t)(m0 + mi * 16 + (lane & 15)) * 128 +
                                         k16 * 32 + (lane >> 4) * 16);
                LDMX4(af[mi], addr);
            }
            uint32_t bf[4][4];
#pragma unroll
            for (int nj = 0; nj < 4; nj++) {
                uint32_t addr = Bb + swz((uint32_t)(n0 + nj * 16 + ro) * 128 + k16 * 32 + kb);
                LDMX4(bf[nj], addr);
            }
#pragma unroll
            for (int mi = 0; mi < 2; mi++)
#pragma unroll
                for (int jj = 0; jj < 8; jj++)
                    MMA16816(acc[mi][jj], af[mi], &bf[jj >> 1][(jj & 1) * 2]);
        }
        __syncthreads();
        if (kt + NSTG < NKT) {
            uint32_t Ab2 = sb + (kt % NSTG) * STB, Bb2 = Ab2 + 16384;
            const char* a = gA + (kt + NSTG) * 128;
            const char* b = gB + (kt + NSTG) * 128;
#pragma unroll
            for (int i = 0; i < 4; i++) {
                cpa16(Ab2 + swz(so + i * 16), a + i * 16);
                cpa16(Bb2 + swz(so + i * 16), b + i * 16);
            }
        }
        asm volatile("cp.async.commit_group;" ::: "memory");
    }

    int qr = lane >> 2, qc = (lane & 3) * 2;

    if (WHICH == 2) {
#pragma unroll
        for (int mi = 0; mi < 2; mi++) {
#pragma unroll
            for (int half = 0; half < 2; half++) {
                int row = mb + m0 + mi * 16 + qr + half * 8;
                if (row >= M) continue;
                __half* dst = g_pA + (size_t)row * KP;
#pragma unroll
                for (int jj = 0; jj < 8; jj++) {
                    int gn = nb + n0 + jj * 8 + qc;
                    float2 bb = *(const float2*)(bias + gn);
                    float f0 = fmaxf(acc[mi][jj][half * 2 + 0] + bb.x, 0.f);
                    float f1 = fmaxf(acc[mi][jj][half * 2 + 1] + bb.y, 0.f);
                    *(__half2*)(dst + gn) =
                        __halves2half2(__float2half_rn(f0), __float2half_rn(f1));
                }
            }
        }
    } else {
        float* sred = (float*)smem;
        float dsum[2][2];
#pragma unroll
        for (int mi = 0; mi < 2; mi++) {
#pragma unroll
            for (int half = 0; half < 2; half++) {
                int row = mb + m0 + mi * 16 + qr + half * 8;
                float dot = 0.f;
                if (row < M) {
                    int s = sst[row], l = sln[row];
                    const __half* T0 = g_TposH + (size_t)(OFF_START + s) * 512;
                    const __half* T1 = g_TposH + (size_t)(OFF_END + s + l) * 512;
                    const __half* T2 = g_TposH + (size_t)(OFF_LEN + l) * 512;
                    const __half* T3 = g_TposH + (size_t)(OFF_MID + 2 * s + l) * 512;
#pragma unroll
                    for (int jj = 0; jj < 8; jj++) {
                        int gn = nb + n0 + jj * 8 + qc;
                        float2 t0 = __half22float2(*(const __half2*)(T0 + gn));
                        float2 t1 = __half22float2(*(const __half2*)(T1 + gn));
                        float2 t2 = __half22float2(*(const __half2*)(T2 + gn));
                        float2 t3 = __half22float2(*(const __half2*)(T3 + gn));
                        float2 bb = *(const float2*)(bias + gn);
                        float2 w1 = *(const float2*)(ww1 + gn);
                        float v0 = fmaxf(acc[mi][jj][half * 2 + 0] + bb.x +
                                         t0.x + t1.x + t2.x + t3.x, 0.f);
                        float v1 = fmaxf(acc[mi][jj][half * 2 + 1] + bb.y +
                                         t0.y + t1.y + t2.y + t3.y, 0.f);
                        dot += v0 * w1.x + v1 * w1.y;
                    }
                }
                dot += __shfl_xor_sync(0xffffffff, dot, 1);
                dot += __shfl_xor_sync(0xffffffff, dot, 2);
                dsum[mi][half] = dot;
            }
        }
        __syncthreads();
        if ((lane & 3) == 0) {
#pragma unroll
            for (int mi = 0; mi < 2; mi++)
#pragma unroll
                for (int half = 0; half < 2; half++)
                    sred[wn * 128 + m0 + mi * 16 + qr + half * 8] = dsum[mi][half];
        }
        __syncthreads();
        if (tid < 128) {
            int row = mb + tid;
            if (row < M) g_partial[row * 4 + blockIdx.x] = sred[tid] + sred[128 + tid];
        }
    }
}

// ---------------- final combine ----------------
__global__ void k_final(const float* __restrict__ wb1, float* __restrict__ out, int M) {
    int c = blockIdx.x * 256 + threadIdx.x;
    if (c < M)
        out[c] = g_partial[c * 4 + 0] + g_partial[c * 4 + 1] +
                 g_partial[c * 4 + 2] + g_partial[c * 4 + 3] + wb1[0];
}

// ---------------- launch ----------------
extern "C" void kernel_launch(void* const* d_in, const int* in_sizes, int n_in,
                              void* d_out, int out_size) {
    const int*   sent = (const int*)d_in[0];
    const int*   tags = (const int*)d_in[1];
    const int*   sst  = (const int*)d_in[2];
    const int*   sln  = (const int*)d_in[3];
    const float* Wwrd = (const float*)d_in[4];
    const float* Wpos = (const float*)d_in[5];
    const float* w0   = (const float*)d_in[6];
    const float* b0   = (const float*)d_in[7];
    const float* w1   = (const float*)d_in[8];
    const float* b1   = (const float*)d_in[9];
    const float* ww0  = (const float*)d_in[10];
    const float* wb0  = (const float*)d_in[11];
    const float* ww1  = (const float*)d_in[12];
    const float* wb1  = (const float*)d_in[13];
    float* out = (float*)d_out;
    int M = in_sizes[2];

    cudaFuncSetAttribute(k_mmW, cudaFuncAttributeMaxDynamicSharedMemorySize, SMEM_TOTAL);
    cudaFuncSetAttribute(k_mm<2>, cudaFuncAttributeMaxDynamicSharedMemorySize, SMEM_TOTAL);
    cudaFuncSetAttribute(k_mm<3>, cudaFuncAttributeMaxDynamicSharedMemorySize, SMEM_TOTAL);

    k_segsum<<<dim3(NSEG, 2), 256>>>(sent, tags, Wwrd, Wpos);
    k_segscan<<<1, 512>>>();
    k_csum<<<dim3(NSEG, 2), 256>>>(sent, tags, Wwrd, Wpos);
    k_prepwT<<<dim3(16, 16), 256>>>(w1, ww0, w0);
    k_tables<<<dim3(64, 2, 4), 256>>>(ww0);
    k_mmW<<<dim3(4, (MW + 127) / 128, 2), 256, SMEM_TOTAL>>>(MW);
    k_buildA<<<dim3(NTOK, 2), 128>>>(b0);

    int mtiles = (M + 127) / 128;
    k_mm<2><<<dim3(4, mtiles), 256, SMEM_TOTAL>>>(b1, nullptr, nullptr, nullptr, M);
    k_mm<3><<<dim3(4, mtiles), 256, SMEM_TOTAL>>>(wb0, ww1, sst, sln, M);

    k_final<<<(M + 255) / 256, 256>>>(wb1, out, M);
}